// round 8
// baseline (speedup 1.0000x reference)
#include <cuda_runtime.h>
#include <cstdint>

// Problem constants
#define HID   1024
#define INP   128
#define NBAT  32
#define LSTEP 2048
#define KTOT  1152            // 1024 (h) + 128 (x)
#define COLS  64              // hidden columns per CTA (lane covers 2)
#define ROWSP 2               // batch rows per PHASE (group)
#define NCOLB 16              // column blocks
#define NGRP  16              // 16 groups of 2 rows
#define GRID  128             // 16 colblocks x 8 group-pairs (single wave)
#define NTHR  512
#define NWARP 16
#define KW    72              // k per warp
#define NCH   18              // chunks of 4k
#define NWF   36              // f32x2 W regs (col0)

// Per-GROUP accumulating flag: each CTA RED-adds 1 per step of that group.
// Pollers wait for base + 16*step. Monotonic across replays (wrap-safe cmp).
__device__ unsigned g_flag[NGRP];

__device__ __forceinline__ unsigned long long fma2(unsigned long long a,
                                                   unsigned long long b,
                                                   unsigned long long c) {
    unsigned long long d;
    asm("fma.rn.f32x2 %0, %1, %2, %3;" : "=l"(d) : "l"(a), "l"(b), "l"(c));
    return d;
}

__device__ __forceinline__ unsigned long long pack2(float x, float y) {
    unsigned long long r;
    asm("mov.b64 %0, {%1, %2};" : "=l"(r) : "f"(x), "f"(y));
    return r;
}

__device__ __forceinline__ float unpack_sum(unsigned long long v) {
    float lo, hi;
    asm("mov.b64 {%0, %1}, %2;" : "=f"(lo), "=f"(hi) : "l"(v));
    return lo + hi;
}

// smem layout (floats):
//   Ws   [288][32][4]       : 36864  (col1 W; [w*NCH+ch][lane][4k]) - shared by phases
//   HP   [2][ROWSP][KTOT]   :  4608  (double buffer: phase A / phase B operands)
//   part [ROWSP][COLS][17]  :  2176
//   bias [COLS]             :    64
#define SM_WS  0
#define HPSZ   (ROWSP * KTOT)
#define SM_HP  (288 * 32 * 4)
#define SM_P   (SM_HP + 2 * HPSZ)
#define PSTR   17
#define SM_B   (SM_P + ROWSP * COLS * PSTR)
#define SM_TOT (SM_B + COLS)            // 43712 floats = 174848 bytes

__global__ void __launch_bounds__(NTHR, 1)
reservoir_persistent(const float* __restrict__ input,   // (L, N, I)
                     const float* __restrict__ h_init,  // (N, H)
                     const float* __restrict__ W_in,    // (H, I)
                     const float* __restrict__ bias,    // (H)
                     const float* __restrict__ W_h,     // (H, H)
                     float* __restrict__ out)           // (L, N, H)
{
    extern __shared__ float smem[];
    float* Ws     = smem + SM_WS;
    float* HP     = smem + SM_HP;
    float* part_s = smem + SM_P;
    float* bias_s = smem + SM_B;

    const int tid = threadIdx.x;
    const int bx  = blockIdx.x;
    const int cb  = bx & (NCOLB - 1);   // column block (0..15)
    const int gp  = bx >> 4;            // group pair (0..7)
    const int j0  = cb * COLS;
    const int gA  = 2 * gp;             // phase-0 group
    const int gB  = 2 * gp + 1;         // phase-1 group
    const int n0A = gA * ROWSP;         // rows 4gp, 4gp+1
    const int n0B = gB * ROWSP;         // rows 4gp+2, 4gp+3

    // Epoch bases: read IMMEDIATELY (before any CTA can arrive this launch).
    const unsigned baseA = *(volatile unsigned*)&g_flag[gA];
    const unsigned baseB = *(volatile unsigned*)&g_flag[gB];

    const int w    = tid >> 5;          // warp = k-slice (72k)
    const int lane = tid & 31;
    const int k0   = w * KW;
    const int col0 = j0 + lane;         // W in registers
    // col1 = j0 + 32 + lane            // W in shared

    // ---- One-time: W col0 into regs (f32x2 packed; k0 & 1024 both even) ----
    unsigned long long w0[NWF];
    #pragma unroll
    for (int i = 0; i < NWF; ++i) {
        int k = k0 + 2 * i;
        float2 v;
        if (k < HID) v = *(const float2*)(W_h + (size_t)col0 * HID + k);
        else         v = *(const float2*)(W_in + (size_t)col0 * INP + (k - HID));
        w0[i] = pack2(v.x, v.y);
    }
    // ---- One-time: W col1 into shared: Ws[cg][l][kk] ----
    for (int i = tid; i < 288 * 32 * 4; i += NTHR) {
        int kk = i & 3;
        int l  = (i >> 2) & 31;
        int cg = i >> 7;
        int k  = 4 * cg + kk;
        int cl = j0 + 32 + l;
        float v = (k < HID) ? W_h[(size_t)cl * HID + k]
                            : W_in[(size_t)cl * INP + (k - HID)];
        Ws[i] = v;
    }
    if (tid < COLS) bias_s[tid] = bias[j0 + tid];

    // ---- Prologue: stage HP[0] = [h_init rows A | x_A(0)] ----
    {
        int n = tid >> 8, q = tid & 255;               // 512 thr -> 2 rows x 256 f4
        float4 v = ((const float4*)(h_init + (size_t)(n0A + n) * HID))[q];
        *(float4*)(HP + 0 * HPSZ + n * KTOT + 4 * q) = v;
        if (tid < 64) {
            int xn = tid >> 5, xq = tid & 31;
            float4 xv = ((const float4*)(input + (size_t)(n0A + xn) * INP))[xq];
            *(float4*)(HP + 0 * HPSZ + xn * KTOT + HID + 4 * xq) = xv;
        }
    }
    __syncthreads();

    const ulonglong2* wsp = (const ulonglong2*)Ws + (size_t)(w * NCH) * 32 + lane;
    const int rn = tid >> 6;            // reduce row (0..1), first 128 thr
    const int rj = tid & 63;            // reduce col (0..63)
    const int sn = tid >> 8, sq = tid & 255;     // stage h indices
    const int xn = tid >> 5, xq = tid & 31;      // stage x indices (tid<64)

    for (int t = 0; t < LSTEP; ++t) {
        #pragma unroll
        for (int p = 0; p < 2; ++p) {
            const int grp_cur   = (p == 0) ? gA : gB;
            const int grp_oth   = (p == 0) ? gB : gA;
            const int n0_cur    = (p == 0) ? n0A : n0B;
            const int n0_oth    = (p == 0) ? n0B : n0A;
            const unsigned bcur = (p == 0) ? baseA : baseB;
            const unsigned both = (p == 0) ? baseB : baseA;
            const int ss        = (p == 0) ? (t - 1) : t;   // other's h step
            const bool do_stage = (ss + 1) < LSTEP;

            // ---- [stage-other, part 1] poll + LDG into registers ----
            // ALL threads poll the SAME flag (each verifies the full condition
            // itself -> safe, unlike per-lane split flags). Expected instant:
            // producers had a full phase of slack.
            float4 hreg, xreg;
            if (do_stage) {
                const unsigned tgt = both + (unsigned)(NCOLB * (ss + 1));
                volatile unsigned* fp = (volatile unsigned*)&g_flag[grp_oth];
                unsigned v = *fp;
                while ((int)(v - tgt) < 0) v = *fp;
                __threadfence();   // acquire
                const float* hsrc = (ss < 0)
                    ? (h_init + (size_t)n0_oth * HID)
                    : (out + ((size_t)ss * NBAT + n0_oth) * HID);
                hreg = __ldcg((const float4*)(hsrc + (size_t)sn * HID) + sq);
                if (tid < 64)
                    xreg = *((const float4*)(input +
                             ((size_t)(ss + 1) * NBAT + n0_oth + xn) * INP) + xq);
            }

            // ---- Compute current phase from HP[p] ----
            const char* ab = (const char*)(HP + p * HPSZ) + (size_t)k0 * 4;
            unsigned long long acc0 = 0, acc1 = 0, acc2 = 0, acc3 = 0;
            #pragma unroll
            for (int ch = 0; ch < NCH; ++ch) {
                ulonglong2 wv = wsp[ch * 32];
                ulonglong2 a0 = *(const ulonglong2*)(ab + 16 * ch);
                ulonglong2 a1 = *(const ulonglong2*)(ab + KTOT * 4 + 16 * ch);
                acc0 = fma2(a0.x, w0[2 * ch], acc0);
                acc0 = fma2(a0.y, w0[2 * ch + 1], acc0);
                acc1 = fma2(a1.x, w0[2 * ch], acc1);
                acc1 = fma2(a1.y, w0[2 * ch + 1], acc1);
                acc2 = fma2(a0.x, wv.x, acc2);
                acc2 = fma2(a0.y, wv.y, acc2);
                acc3 = fma2(a1.x, wv.x, acc3);
                acc3 = fma2(a1.y, wv.y, acc3);
            }

            // ---- [stage-other, part 2] STS (scoreboard absorbed by compute) ----
            if (do_stage) {
                float* HPo = HP + (1 - p) * HPSZ;
                *(float4*)(HPo + sn * KTOT + 4 * sq) = hreg;
                if (tid < 64)
                    *(float4*)(HPo + xn * KTOT + HID + 4 * xq) = xreg;
            }

            // ---- Dump partials ----
            part_s[(0 * COLS + lane) * PSTR + w]      = unpack_sum(acc0);
            part_s[(1 * COLS + lane) * PSTR + w]      = unpack_sum(acc1);
            part_s[(0 * COLS + 32 + lane) * PSTR + w] = unpack_sum(acc2);
            part_s[(1 * COLS + 32 + lane) * PSTR + w] = unpack_sum(acc3);
            __syncthreads();

            // ---- Reduce 16 partials + bias + tanh + store h(t) ----
            if (tid < 128) {
                float s = bias_s[rj];
                #pragma unroll
                for (int ww = 0; ww < NWARP; ++ww)
                    s += part_s[(rn * COLS + rj) * PSTR + ww];
                float hv = tanhf(s);
                out[((size_t)t * NBAT + n0_cur + rn) * HID + j0 + rj] = hv;
            }
            __syncthreads();

            // ---- Arrive current phase (release) ----
            if (tid == 0) {
                __threadfence();
                atomicAdd((unsigned*)&g_flag[grp_cur], 1u);
            }
            (void)bcur;
        }
    }
}

extern "C" void kernel_launch(void* const* d_in, const int* in_sizes, int n_in,
                              void* d_out, int out_size) {
    (void)in_sizes; (void)n_in; (void)out_size;
    const float* input  = (const float*)d_in[0];  // (2048, 32, 128)
    const float* h_init = (const float*)d_in[1];  // (32, 1024)
    const float* W_in   = (const float*)d_in[2];  // (1024, 128)
    const float* bias   = (const float*)d_in[3];  // (1024)
    const float* W_h    = (const float*)d_in[4];  // (1024, 1024)
    float* out = (float*)d_out;                   // (2048, 32, 1024)

    cudaFuncSetAttribute(reservoir_persistent,
                         cudaFuncAttributeMaxDynamicSharedMemorySize,
                         SM_TOT * (int)sizeof(float));
    reservoir_persistent<<<GRID, NTHR, SM_TOT * sizeof(float)>>>(
        input, h_init, W_in, bias, W_h, out);
}

// round 9
// speedup vs baseline: 1.2258x; 1.2258x over previous
#include <cuda_runtime.h>
#include <cstdint>

// Problem constants
#define HID    1024
#define INP    128
#define NBAT   32
#define LSTEP  2048
#define KTOT   1152            // 1024 (h) + 128 (x)
#define COLS   64              // hidden columns per CTA (lane covers 2)
#define ROWSB  4               // batch rows per CTA (= per cluster)
#define CLUSTER 16             // CTAs per cluster = column blocks
#define GRID   128             // 8 clusters x 16
#define NTHR   512
#define NWARP  16
#define KW     72              // k per warp
#define NCH    18              // chunks of 4k
#define NWF    36              // f32x2 W regs (col0)

__device__ __forceinline__ unsigned long long fma2(unsigned long long a,
                                                   unsigned long long b,
                                                   unsigned long long c) {
    unsigned long long d;
    asm("fma.rn.f32x2 %0, %1, %2, %3;" : "=l"(d) : "l"(a), "l"(b), "l"(c));
    return d;
}

__device__ __forceinline__ unsigned long long pack2(float x, float y) {
    unsigned long long r;
    asm("mov.b64 %0, {%1, %2};" : "=l"(r) : "f"(x), "f"(y));
    return r;
}

__device__ __forceinline__ float unpack_sum(unsigned long long v) {
    float lo, hi;
    asm("mov.b64 {%0, %1}, %2;" : "=f"(lo), "=f"(hi) : "l"(v));
    return lo + hi;
}

__device__ __forceinline__ uint32_t smem_u32(const void* p) {
    uint32_t a;
    asm("{ .reg .u64 t; cvta.to.shared.u64 t, %1; cvt.u32.u64 %0, t; }"
        : "=r"(a) : "l"(p));
    return a;
}

__device__ __forceinline__ uint32_t mapa_rank(uint32_t laddr, uint32_t rank) {
    uint32_t r;
    asm("mapa.shared::cluster.u32 %0, %1, %2;" : "=r"(r) : "r"(laddr), "r"(rank));
    return r;
}

__device__ __forceinline__ void st_cluster_f32(uint32_t addr, float v) {
    asm volatile("st.shared::cluster.b32 [%0], %1;"
                 :: "r"(addr), "r"(__float_as_uint(v)) : "memory");
}

// smem layout (floats):
//   Ws   [288][32][4]     : 36864  (col1 W; [w*NCH+ch][lane][4k])
//   HP   [2][ROWSB][KTOT] :  9216  (ping-pong operand buffer [h | x])
//   part [ROWSB][COLS][17]:  4352  (conflict-free reduce scratch)
//   bias [COLS]           :    64
#define HPSZ   (ROWSB * KTOT)
#define SM_WS  0
#define SM_HP  (288 * 32 * 4)
#define SM_P   (SM_HP + 2 * HPSZ)
#define PSTR   17
#define SM_B   (SM_P + ROWSB * COLS * PSTR)
#define SM_TOT (SM_B + COLS)            // 50496 floats = 201984 bytes

__global__ void __launch_bounds__(NTHR, 1) __cluster_dims__(CLUSTER, 1, 1)
reservoir_persistent(const float* __restrict__ input,   // (L, N, I)
                     const float* __restrict__ h_init,  // (N, H)
                     const float* __restrict__ W_in,    // (H, I)
                     const float* __restrict__ bias,    // (H)
                     const float* __restrict__ W_h,     // (H, H)
                     float* __restrict__ out)           // (L, N, H)
{
    extern __shared__ float smem[];
    float* Ws     = smem + SM_WS;
    float* HP     = smem + SM_HP;
    float* part_s = smem + SM_P;
    float* bias_s = smem + SM_B;

    const int tid = threadIdx.x;
    const int bx  = blockIdx.x;
    const int c   = bx & (CLUSTER - 1); // column block = cluster rank
    const int g   = bx >> 4;            // batch group = cluster id
    const int j0  = c * COLS;
    const int n0  = g * ROWSB;

    const int w    = tid >> 5;          // warp = k-slice (72 k)
    const int lane = tid & 31;
    const int k0   = w * KW;
    const int col0 = j0 + lane;         // W in registers
    // col1 = j0 + 32 + lane            // W in shared

    // ---- One-time: W col0 into regs (f32x2 packed; k0 & 1024 both even) ----
    unsigned long long w0[NWF];
    #pragma unroll
    for (int i = 0; i < NWF; ++i) {
        int k = k0 + 2 * i;
        float2 v;
        if (k < HID) v = *(const float2*)(W_h + (size_t)col0 * HID + k);
        else         v = *(const float2*)(W_in + (size_t)col0 * INP + (k - HID));
        w0[i] = pack2(v.x, v.y);
    }
    // ---- One-time: W col1 into shared: Ws[cg][l][kk] ----
    for (int i = tid; i < 288 * 32 * 4; i += NTHR) {
        int kk = i & 3;
        int l  = (i >> 2) & 31;
        int cg = i >> 7;
        int k  = 4 * cg + kk;
        int cl = j0 + 32 + l;
        float v = (k < HID) ? W_h[(size_t)cl * HID + k]
                            : W_in[(size_t)cl * INP + (k - HID)];
        Ws[i] = v;
    }
    if (tid < COLS) bias_s[tid] = bias[j0 + tid];

    // ---- Prologue: HP[0] = [h_init rows | x(0)] (all local) ----
    #pragma unroll
    for (int rep = 0; rep < 2; ++rep) {
        int i = tid + rep * NTHR;       // 0..1023 -> 4 rows x 256 f4
        int n = i >> 8, q = i & 255;
        float4 v = ((const float4*)(h_init + (size_t)(n0 + n) * HID))[q];
        *(float4*)(HP + n * KTOT + 4 * q) = v;
    }
    if (tid < 128) {
        int n = tid >> 5, q = tid & 31;
        float4 xv = ((const float4*)(input + (size_t)(n0 + n) * INP))[q];
        *(float4*)(HP + n * KTOT + HID + 4 * q) = xv;
    }
    __syncthreads();

    const ulonglong2* wsp = (const ulonglong2*)Ws + (size_t)(w * NCH) * 32 + lane;
    const int rn = tid >> 6;            // reduce row (0..3), first 256 thr
    const int rj = tid & 63;            // reduce col (0..63)
    const uint32_t hp_u32 = smem_u32(HP);

    for (int t = 0; t < LSTEP; ++t) {
        const int p  = t & 1;
        const int nb = p ^ 1;

        // ---- Stage x(t+1) into HP[nb] (local; overlaps compute) ----
        if (tid < 128 && (t + 1) < LSTEP) {
            int n = tid >> 5, q = tid & 31;
            float4 xv = ((const float4*)(input +
                         ((size_t)(t + 1) * NBAT + n0 + n) * INP))[q];
            *(float4*)(HP + nb * HPSZ + n * KTOT + HID + 4 * q) = xv;
        }

        // ---- Compute from HP[p]: h broadcast LDS, W reg (col0) + smem (col1) ----
        const char* ab = (const char*)(HP + p * HPSZ) + (size_t)k0 * 4;
        unsigned long long acc[2 * ROWSB];
        #pragma unroll
        for (int i = 0; i < 2 * ROWSB; ++i) acc[i] = 0ull;

        #pragma unroll
        for (int ch = 0; ch < NCH; ++ch) {
            ulonglong2 wv = wsp[ch * 32];
            #pragma unroll
            for (int r = 0; r < ROWSB; ++r) {
                ulonglong2 a = *(const ulonglong2*)(ab + r * (KTOT * 4) + 16 * ch);
                acc[2 * r]     = fma2(a.x, w0[2 * ch],     acc[2 * r]);
                acc[2 * r]     = fma2(a.y, w0[2 * ch + 1], acc[2 * r]);
                acc[2 * r + 1] = fma2(a.x, wv.x,           acc[2 * r + 1]);
                acc[2 * r + 1] = fma2(a.y, wv.y,           acc[2 * r + 1]);
            }
        }

        // ---- Dump partials: part[r][col][w], stride-17 conflict-free ----
        #pragma unroll
        for (int r = 0; r < ROWSB; ++r) {
            part_s[(r * COLS + lane) * PSTR + w]      = unpack_sum(acc[2 * r]);
            part_s[(r * COLS + 32 + lane) * PSTR + w] = unpack_sum(acc[2 * r + 1]);
        }
        __syncthreads();

        // ---- Reduce 16 partials + bias + tanh; STG out; DSMEM push ----
        if (tid < 256) {
            float s = bias_s[rj];
            #pragma unroll
            for (int ww = 0; ww < NWARP; ++ww)
                s += part_s[(rn * COLS + rj) * PSTR + ww];
            float hv = tanhf(s);
            out[((size_t)t * NBAT + n0 + rn) * HID + j0 + rj] = hv;

            if ((t + 1) < LSTEP) {
                // Push h(t)[rn, j0+rj] into every peer's HP[nb]
                uint32_t loff = hp_u32 +
                    (uint32_t)(nb * HPSZ + rn * KTOT + j0 + rj) * 4u;
                #pragma unroll
                for (int r = 0; r < CLUSTER; ++r)
                    st_cluster_f32(mapa_rank(loff, (uint32_t)r), hv);
            }
        }
        __syncthreads();   // part_s reusable; all pushes issued

        // ---- Cluster barrier: release our pushes / acquire peers' ----
        asm volatile("barrier.cluster.arrive.aligned;" ::: "memory");
        asm volatile("barrier.cluster.wait.aligned;"   ::: "memory");
    }
}

extern "C" void kernel_launch(void* const* d_in, const int* in_sizes, int n_in,
                              void* d_out, int out_size) {
    (void)in_sizes; (void)n_in; (void)out_size;
    const float* input  = (const float*)d_in[0];  // (2048, 32, 128)
    const float* h_init = (const float*)d_in[1];  // (32, 1024)
    const float* W_in   = (const float*)d_in[2];  // (1024, 128)
    const float* bias   = (const float*)d_in[3];  // (1024)
    const float* W_h    = (const float*)d_in[4];  // (1024, 1024)
    float* out = (float*)d_out;                   // (2048, 32, 1024)

    cudaFuncSetAttribute(reservoir_persistent,
                         cudaFuncAttributeMaxDynamicSharedMemorySize,
                         SM_TOT * (int)sizeof(float));
    cudaFuncSetAttribute(reservoir_persistent,
                         cudaFuncAttributeNonPortableClusterSizeAllowed, 1);
    reservoir_persistent<<<GRID, NTHR, SM_TOT * sizeof(float)>>>(
        input, h_init, W_in, bias, W_h, out);
}